// round 9
// baseline (speedup 1.0000x reference)
#include <cuda_runtime.h>
#include <cstdint>

#define NN 20000
#define EE 10000
#define IC 128
#define OC 64
#define SPLIT2 8

// Scratch (no allocations allowed)
__device__ uint2 g_xthl[NN * OC];    // xt as tf32 (hi, lo)
__device__ float g_edge[EE * OC];    // f32 accumulator (atomics)
__device__ uint2 g_edgehl[EE * OC];  // edge/de as tf32 (hi, lo)
__device__ float g_de[EE];

// ---------------------------------------------------------------- helpers
__device__ __forceinline__ uint32_t f2tf(float x) {
    uint32_t r;
    asm("cvt.rna.tf32.f32 %0, %1;" : "=r"(r) : "f"(x));
    return r;
}
__device__ __forceinline__ uint2 f2hl(float x) {
    uint32_t h = f2tf(x);
    uint32_t l = f2tf(x - __uint_as_float(h));
    return make_uint2(h, l);
}
__device__ __forceinline__ void mma8(float* c,
                                     uint32_t a0, uint32_t a1, uint32_t a2, uint32_t a3,
                                     uint32_t b0, uint32_t b1) {
    asm volatile(
        "mma.sync.aligned.m16n8k8.row.col.f32.tf32.tf32.f32 "
        "{%0,%1,%2,%3},{%4,%5,%6,%7},{%8,%9},{%0,%1,%2,%3};"
        : "+f"(c[0]), "+f"(c[1]), "+f"(c[2]), "+f"(c[3])
        : "r"(a0), "r"(a1), "r"(a2), "r"(a3), "r"(b0), "r"(b1));
}

// ---------------------------------------------------------------- zero
__global__ void zero_k() {
    int i = blockIdx.x * 256 + threadIdx.x;
    if (i < EE * OC) g_edge[i] = 0.0f;
    if (i < EE)      g_de[i]   = 0.0f;
}

// ---------------------------------------------------------------- xt = x @ theta -> hi/lo
__global__ void xt_k(const float* __restrict__ x, const float* __restrict__ th) {
    __shared__ float ths[IC * OC];
    int tid = threadIdx.x;
    #pragma unroll
    for (int i = tid; i < IC * OC; i += 256) ths[i] = th[i];
    __syncthreads();

    int n = blockIdx.x * 4 + (tid >> 6);
    int c = tid & 63;
    const float* xr = x + (size_t)n * IC;
    float acc = 0.0f;
    #pragma unroll 8
    for (int k = 0; k < IC; ++k) acc += xr[k] * ths[k * OC + c];
    g_xthl[n * OC + c] = f2hl(acc);
}

// ---------------------------------------------------------------- pass2: edge += H^T @ xt ; de += colsum(H)
struct SmemP2 {
    uint2 As[32][132];   // [k][e_local] interleaved (hi,lo); stride 132 uint2
    uint2 Bs[32][66];    // [k][c]
    float dsm[8][128];
};

__global__ __launch_bounds__(256) void pass2_k(const float* __restrict__ H) {
    extern __shared__ char smem_raw[];
    SmemP2& S = *reinterpret_cast<SmemP2*>(smem_raw);

    int tid  = threadIdx.x;
    int lane = tid & 31, wid = tid >> 5;
    int e0   = blockIdx.x * 128;
    int wm   = wid >> 1, wn = wid & 1;
    int mo   = wm * 32,  no = wn * 32;
    int g    = lane >> 2, tg = lane & 3;

    const int TILES = NN / 32;                       // 625
    const int TPC   = (TILES + SPLIT2 - 1) / SPLIT2; // 79
    int t0 = blockIdx.y * TPC;
    int t1 = t0 + TPC; if (t1 > TILES) t1 = TILES;

    int am = 4 * lane;
    bool eok = (e0 + am + 4 <= EE);
    int bk = tid >> 4, bn = 4 * (tid & 15);          // bn in uint2 units (channels)

    float4 pa[4];
    uint4  pb[2][2];
    float dsum[4] = {0.f, 0.f, 0.f, 0.f};
    float c[2][4][4];
    #pragma unroll
    for (int mi = 0; mi < 2; ++mi)
        #pragma unroll
        for (int ni = 0; ni < 4; ++ni)
            #pragma unroll
            for (int j = 0; j < 4; ++j) c[mi][ni][j] = 0.f;

    // prefetch first tile
    {
        int t = t0;
        #pragma unroll
        for (int it = 0; it < 4; ++it) {
            int k = t * 32 + wid + 8 * it;
            pa[it] = eok ? *(const float4*)&H[(long)k * EE + e0 + am]
                         : make_float4(0.f, 0.f, 0.f, 0.f);
        }
        #pragma unroll
        for (int it = 0; it < 2; ++it) {
            long base = (long)(t * 32 + bk + 16 * it) * OC + bn;
            pb[it][0] = *(const uint4*)&g_xthl[base];
            pb[it][1] = *(const uint4*)&g_xthl[base + 2];
        }
    }

    for (int t = t0; t < t1; ++t) {
        // stage current (convert A at staging)
        #pragma unroll
        for (int it = 0; it < 4; ++it) {
            int r = wid + 8 * it;
            dsum[0] += pa[it].x; dsum[1] += pa[it].y;
            dsum[2] += pa[it].z; dsum[3] += pa[it].w;
            uint2 h0 = f2hl(pa[it].x), h1 = f2hl(pa[it].y);
            uint2 h2 = f2hl(pa[it].z), h3 = f2hl(pa[it].w);
            *(uint4*)&S.As[r][am]     = make_uint4(h0.x, h0.y, h1.x, h1.y);
            *(uint4*)&S.As[r][am + 2] = make_uint4(h2.x, h2.y, h3.x, h3.y);
        }
        #pragma unroll
        for (int it = 0; it < 2; ++it) {
            int r = bk + 16 * it;
            *(uint4*)&S.Bs[r][bn]     = pb[it][0];
            *(uint4*)&S.Bs[r][bn + 2] = pb[it][1];
        }
        __syncthreads();

        // prefetch next
        if (t + 1 < t1) {
            #pragma unroll
            for (int it = 0; it < 4; ++it) {
                int k = (t + 1) * 32 + wid + 8 * it;
                pa[it] = eok ? *(const float4*)&H[(long)k * EE + e0 + am]
                             : make_float4(0.f, 0.f, 0.f, 0.f);
            }
            #pragma unroll
            for (int it = 0; it < 2; ++it) {
                long base = (long)((t + 1) * 32 + bk + 16 * it) * OC + bn;
                pb[it][0] = *(const uint4*)&g_xthl[base];
                pb[it][1] = *(const uint4*)&g_xthl[base + 2];
            }
        }

        // compute: pure LDS.64 + MMA
        #pragma unroll
        for (int ko = 0; ko < 32; ko += 8) {
            uint2 b0[4], b1[4];
            #pragma unroll
            for (int ni = 0; ni < 4; ++ni) {
                b0[ni] = S.Bs[ko + tg][no + ni * 8 + g];
                b1[ni] = S.Bs[ko + tg + 4][no + ni * 8 + g];
            }
            #pragma unroll
            for (int mi = 0; mi < 2; ++mi) {
                int mb = mo + mi * 16;
                uint2 a0 = S.As[ko + tg][mb + g];
                uint2 a1 = S.As[ko + tg][mb + g + 8];
                uint2 a2 = S.As[ko + tg + 4][mb + g];
                uint2 a3 = S.As[ko + tg + 4][mb + g + 8];
                #pragma unroll
                for (int ni = 0; ni < 4; ++ni) {
                    mma8(c[mi][ni], a0.x, a1.x, a2.x, a3.x, b0[ni].x, b1[ni].x);
                    mma8(c[mi][ni], a0.x, a1.x, a2.x, a3.x, b0[ni].y, b1[ni].y);
                    mma8(c[mi][ni], a0.y, a1.y, a2.y, a3.y, b0[ni].x, b1[ni].x);
                }
            }
        }
        __syncthreads();
    }

    // colsum reduction -> g_de
    #pragma unroll
    for (int j = 0; j < 4; ++j) S.dsm[wid][am + j] = dsum[j];
    __syncthreads();
    if (wid == 0) {
        float s[4] = {0.f, 0.f, 0.f, 0.f};
        #pragma unroll
        for (int w = 0; w < 8; ++w)
            #pragma unroll
            for (int j = 0; j < 4; ++j) s[j] += S.dsm[w][am + j];
        #pragma unroll
        for (int j = 0; j < 4; ++j) {
            int e = e0 + am + j;
            if (e < EE) atomicAdd(&g_de[e], s[j]);
        }
    }

    // accumulate edge tiles
    #pragma unroll
    for (int mi = 0; mi < 2; ++mi) {
        #pragma unroll
        for (int ni = 0; ni < 4; ++ni) {
            int er0 = e0 + mo + mi * 16 + g;
            int er1 = er0 + 8;
            int col = no + ni * 8 + 2 * tg;
            if (er0 < EE) {
                atomicAdd(&g_edge[er0 * OC + col],     c[mi][ni][0]);
                atomicAdd(&g_edge[er0 * OC + col + 1], c[mi][ni][1]);
            }
            if (er1 < EE) {
                atomicAdd(&g_edge[er1 * OC + col],     c[mi][ni][2]);
                atomicAdd(&g_edge[er1 * OC + col + 1], c[mi][ni][3]);
            }
        }
    }
}

// ---------------------------------------------------------------- edge/de -> hi/lo
__global__ void div_k() {
    int i = blockIdx.x * 256 + threadIdx.x;
    if (i < EE * OC) {
        float v = g_edge[i] / g_de[i >> 6];
        g_edgehl[i] = f2hl(v);
    }
}

// ---------------------------------------------------------------- pass3: out = (H @ edge) / rowsum(H)
struct SmemP3 {
    uint2 As[128][34];   // [n_local][k] interleaved (hi,lo)
    uint2 Bs[32][66];    // [k][c]
    float dn[128];
};

__global__ __launch_bounds__(256) void pass3_k(const float* __restrict__ H,
                                               float* __restrict__ out) {
    extern __shared__ char smem_raw[];
    SmemP3& S = *reinterpret_cast<SmemP3*>(smem_raw);

    int tid  = threadIdx.x;
    int lane = tid & 31, wid = tid >> 5;
    int n0   = blockIdx.x * 128;
    int wm   = wid >> 1, wn = wid & 1;
    int mo   = wm * 32,  no = wn * 32;
    int g    = lane >> 2, tg = lane & 3;

    int row = tid >> 1, s = tid & 1;
    int gn  = n0 + row;
    bool rok = (gn < NN);
    int bk = tid >> 4, bn = 4 * (tid & 15);

    float4 pa[4];
    uint4  pb[2][2];
    float rsum = 0.f;
    float c[2][4][4];
    #pragma unroll
    for (int mi = 0; mi < 2; ++mi)
        #pragma unroll
        for (int ni = 0; ni < 4; ++ni)
            #pragma unroll
            for (int j = 0; j < 4; ++j) c[mi][ni][j] = 0.f;

    const int KT = (EE + 31) / 32;   // 313

    // prefetch first tile
    {
        #pragma unroll
        for (int i = 0; i < 4; ++i) {
            int k = (s * 4 + i) * 4;
            pa[i] = (rok && k + 4 <= EE) ? *(const float4*)&H[(long)gn * EE + k]
                                         : make_float4(0.f, 0.f, 0.f, 0.f);
        }
        #pragma unroll
        for (int it = 0; it < 2; ++it) {
            int k = bk + 16 * it;
            if (k < EE) {
                long base = (long)k * OC + bn;
                pb[it][0] = *(const uint4*)&g_edgehl[base];
                pb[it][1] = *(const uint4*)&g_edgehl[base + 2];
            } else {
                pb[it][0] = make_uint4(0, 0, 0, 0);
                pb[it][1] = make_uint4(0, 0, 0, 0);
            }
        }
    }

    for (int t = 0; t < KT; ++t) {
        #pragma unroll
        for (int i = 0; i < 4; ++i) {
            rsum += pa[i].x + pa[i].y + pa[i].z + pa[i].w;
            uint2 h0 = f2hl(pa[i].x), h1 = f2hl(pa[i].y);
            uint2 h2 = f2hl(pa[i].z), h3 = f2hl(pa[i].w);
            int kc = (s * 4 + i) * 4;
            *(uint4*)&S.As[row][kc]     = make_uint4(h0.x, h0.y, h1.x, h1.y);
            *(uint4*)&S.As[row][kc + 2] = make_uint4(h2.x, h2.y, h3.x, h3.y);
        }
        #pragma unroll
        for (int it = 0; it < 2; ++it) {
            int r = bk + 16 * it;
            *(uint4*)&S.Bs[r][bn]     = pb[it][0];
            *(uint4*)&S.Bs[r][bn + 2] = pb[it][1];
        }
        __syncthreads();

        if (t + 1 < KT) {
            int k0 = (t + 1) * 32;
            #pragma unroll
            for (int i = 0; i < 4; ++i) {
                int k = k0 + (s * 4 + i) * 4;
                pa[i] = (rok && k + 4 <= EE) ? *(const float4*)&H[(long)gn * EE + k]
                                             : make_float4(0.f, 0.f, 0.f, 0.f);
            }
            #pragma unroll
            for (int it = 0; it < 2; ++it) {
                int k = k0 + bk + 16 * it;
                if (k < EE) {
                    long base = (long)k * OC + bn;
                    pb[it][0] = *(const uint4*)&g_edgehl[base];
                    pb[it][1] = *(const uint4*)&g_edgehl[base + 2];
                } else {
                    pb[it][0] = make_uint4(0, 0, 0, 0);
                    pb[it][1] = make_uint4(0, 0, 0, 0);
                }
            }
        }

        #pragma unroll
        for (int ko = 0; ko < 32; ko += 8) {
            uint2 b0[4], b1[4];
            #pragma unroll
            for (int ni = 0; ni < 4; ++ni) {
                b0[ni] = S.Bs[ko + tg][no + ni * 8 + g];
                b1[ni] = S.Bs[ko + tg + 4][no + ni * 8 + g];
            }
            #pragma unroll
            for (int mi = 0; mi < 2; ++mi) {
                int mb = mo + mi * 16;
                uint2 a0 = S.As[mb + g][ko + tg];
                uint2 a1 = S.As[mb + g + 8][ko + tg];
                uint2 a2 = S.As[mb + g][ko + tg + 4];
                uint2 a3 = S.As[mb + g + 8][ko + tg + 4];
                #pragma unroll
                for (int ni = 0; ni < 4; ++ni) {
                    mma8(c[mi][ni], a0.x, a1.x, a2.x, a3.x, b0[ni].x, b1[ni].x);
                    mma8(c[mi][ni], a0.x, a1.x, a2.x, a3.x, b0[ni].y, b1[ni].y);
                    mma8(c[mi][ni], a0.y, a1.y, a2.y, a3.y, b0[ni].x, b1[ni].x);
                }
            }
        }
        __syncthreads();
    }

    // row degree
    float tot = rsum + __shfl_xor_sync(0xffffffffu, rsum, 1);
    if (s == 0) S.dn[row] = tot;
    __syncthreads();

    #pragma unroll
    for (int mi = 0; mi < 2; ++mi) {
        #pragma unroll
        for (int ni = 0; ni < 4; ++ni) {
            int r0  = mo + mi * 16 + g;
            int r1  = r0 + 8;
            int col = no + ni * 8 + 2 * tg;
            if (n0 + r0 < NN) {
                float inv = 1.0f / S.dn[r0];
                out[(long)(n0 + r0) * OC + col]     = c[mi][ni][0] * inv;
                out[(long)(n0 + r0) * OC + col + 1] = c[mi][ni][1] * inv;
            }
            if (n0 + r1 < NN) {
                float inv = 1.0f / S.dn[r1];
                out[(long)(n0 + r1) * OC + col]     = c[mi][ni][2] * inv;
                out[(long)(n0 + r1) * OC + col + 1] = c[mi][ni][3] * inv;
            }
        }
    }
}

// ---------------------------------------------------------------- launch
extern "C" void kernel_launch(void* const* d_in, const int* in_sizes, int n_in,
                              void* d_out, int out_size) {
    const float* x  = (const float*)d_in[0];   // [N, 128]
    const float* H  = (const float*)d_in[1];   // [N, E]
    const float* th = (const float*)d_in[2];   // [128, 64]
    float* out = (float*)d_out;                // [N, 64]

    // Attribute sets are host-side, not stream ops: graph-capture safe, idempotent.
    cudaFuncSetAttribute(pass2_k, cudaFuncAttributeMaxDynamicSharedMemorySize,
                         (int)sizeof(SmemP2));
    cudaFuncSetAttribute(pass3_k, cudaFuncAttributeMaxDynamicSharedMemorySize,
                         (int)sizeof(SmemP3));

    zero_k<<<(EE * OC + 255) / 256, 256>>>();
    xt_k<<<NN / 4, 256>>>(x, th);
    dim3 g2((EE + 127) / 128, SPLIT2);
    pass2_k<<<g2, 256, sizeof(SmemP2)>>>(H);
    div_k<<<(EE * OC + 255) / 256, 256>>>();
    pass3_k<<<(NN + 127) / 128, 256, sizeof(SmemP3)>>>(H, out);
}

// round 14
// speedup vs baseline: 1.7793x; 1.7793x over previous
#include <cuda_runtime.h>
#include <cstdint>

#define NN 20000
#define EE 10000
#define IC 128
#define OC 64
#define SPLIT2 8
#define CENTER 1.00048828125f   // 1 + 2^-11: centers tf32 truncation error

// Scratch (no allocations allowed)
__device__ float g_xth[NN * OC];    // xt tf32-hi plane
__device__ float g_xtl[NN * OC];    // xt tf32-lo plane
__device__ float g_edge[EE * OC];   // f32 accumulator (atomics)
__device__ float g_edgeh[EE * OC];  // edge tf32-hi plane
__device__ float g_edgel[EE * OC];  // edge tf32-lo plane
__device__ float g_de[EE];

// ---------------------------------------------------------------- helpers
__device__ __forceinline__ uint32_t f2tf(float x) {
    uint32_t r;
    asm("cvt.rna.tf32.f32 %0, %1;" : "=r"(r) : "f"(x));
    return r;
}
__device__ __forceinline__ void mma8(float* c,
                                     uint32_t a0, uint32_t a1, uint32_t a2, uint32_t a3,
                                     uint32_t b0, uint32_t b1) {
    asm volatile(
        "mma.sync.aligned.m16n8k8.row.col.f32.tf32.tf32.f32 "
        "{%0,%1,%2,%3},{%4,%5,%6,%7},{%8,%9},{%0,%1,%2,%3};"
        : "+f"(c[0]), "+f"(c[1]), "+f"(c[2]), "+f"(c[3])
        : "r"(a0), "r"(a1), "r"(a2), "r"(a3), "r"(b0), "r"(b1));
}
__device__ __forceinline__ uint32_t fbits(float x) { return __float_as_uint(x); }

// ---------------------------------------------------------------- zero
__global__ void zero_k() {
    int i = blockIdx.x * 256 + threadIdx.x;
    if (i < EE * OC) g_edge[i] = 0.0f;
    if (i < EE)      g_de[i]   = 0.0f;
}

// ---------------------------------------------------------------- xt = x @ theta -> hi/lo planes
__global__ void xt_k(const float* __restrict__ x, const float* __restrict__ th) {
    __shared__ float ths[IC * OC];
    int tid = threadIdx.x;
    #pragma unroll
    for (int i = tid; i < IC * OC; i += 256) ths[i] = th[i];
    __syncthreads();

    int n = blockIdx.x * 4 + (tid >> 6);
    int c = tid & 63;
    const float* xr = x + (size_t)n * IC;
    float acc = 0.0f;
    #pragma unroll 8
    for (int k = 0; k < IC; ++k) acc += xr[k] * ths[k * OC + c];
    uint32_t h = f2tf(acc);
    uint32_t l = f2tf(acc - __uint_as_float(h));
    g_xth[n * OC + c] = __uint_as_float(h);
    g_xtl[n * OC + c] = __uint_as_float(l);
}

// ---------------------------------------------------------------- pass2: edge += H^T @ xt ; de += colsum(H)
__global__ __launch_bounds__(256, 2) void pass2_k(const float* __restrict__ H) {
    __shared__ float As[32][136];   // [k][e_local] raw(scaled) H; bank-safe stride
    __shared__ float Bh[32][72];    // [k][c] xt hi
    __shared__ float Bl[32][72];    // [k][c] xt lo
    __shared__ float dsm[8][128];

    int tid  = threadIdx.x;
    int lane = tid & 31, wid = tid >> 5;
    int e0   = blockIdx.x * 128;
    int wm   = wid >> 1, wn = wid & 1;
    int mo   = wm * 32,  no = wn * 32;
    int g    = lane >> 2, tg = lane & 3;

    const int TILES = NN / 32;                       // 625
    const int TPC   = (TILES + SPLIT2 - 1) / SPLIT2; // 79
    int t0 = blockIdx.y * TPC;
    int t1 = t0 + TPC; if (t1 > TILES) t1 = TILES;

    int am = 4 * lane;
    bool eok = (e0 + am + 4 <= EE);
    int bk = tid >> 4, bn = 4 * (tid & 15);

    float4 pa[4], pbh[2], pbl[2];
    float dsum[4] = {0.f, 0.f, 0.f, 0.f};
    float c[2][4][4];
    #pragma unroll
    for (int mi = 0; mi < 2; ++mi)
        #pragma unroll
        for (int ni = 0; ni < 4; ++ni)
            #pragma unroll
            for (int j = 0; j < 4; ++j) c[mi][ni][j] = 0.f;

    // prefetch first tile
    {
        int t = t0;
        #pragma unroll
        for (int it = 0; it < 4; ++it) {
            int k = t * 32 + wid + 8 * it;
            pa[it] = eok ? *(const float4*)&H[(long)k * EE + e0 + am]
                         : make_float4(0.f, 0.f, 0.f, 0.f);
        }
        #pragma unroll
        for (int it = 0; it < 2; ++it) {
            long base = (long)(t * 32 + bk + 16 * it) * OC + bn;
            pbh[it] = *(const float4*)&g_xth[base];
            pbl[it] = *(const float4*)&g_xtl[base];
        }
    }

    for (int t = t0; t < t1; ++t) {
        // stage current (raw sums for de; centered-scaled values for MMA)
        #pragma unroll
        for (int it = 0; it < 4; ++it) {
            int r = wid + 8 * it;
            dsum[0] += pa[it].x; dsum[1] += pa[it].y;
            dsum[2] += pa[it].z; dsum[3] += pa[it].w;
            float4 sv;
            sv.x = pa[it].x * CENTER; sv.y = pa[it].y * CENTER;
            sv.z = pa[it].z * CENTER; sv.w = pa[it].w * CENTER;
            *(float4*)&As[r][am] = sv;
        }
        #pragma unroll
        for (int it = 0; it < 2; ++it) {
            int r = bk + 16 * it;
            *(float4*)&Bh[r][bn] = pbh[it];
            *(float4*)&Bl[r][bn] = pbl[it];
        }
        __syncthreads();

        // prefetch next
        if (t + 1 < t1) {
            #pragma unroll
            for (int it = 0; it < 4; ++it) {
                int k = (t + 1) * 32 + wid + 8 * it;
                pa[it] = eok ? *(const float4*)&H[(long)k * EE + e0 + am]
                             : make_float4(0.f, 0.f, 0.f, 0.f);
            }
            #pragma unroll
            for (int it = 0; it < 2; ++it) {
                long base = (long)((t + 1) * 32 + bk + 16 * it) * OC + bn;
                pbh[it] = *(const float4*)&g_xth[base];
                pbl[it] = *(const float4*)&g_xtl[base];
            }
        }

        // compute: A raw (HW-truncated), B hi+lo -> 2 MMAs per tile-step
        #pragma unroll
        for (int ko = 0; ko < 32; ko += 8) {
            uint32_t bh0[4], bh1[4], bl0[4], bl1[4];
            #pragma unroll
            for (int ni = 0; ni < 4; ++ni) {
                bh0[ni] = fbits(Bh[ko + tg][no + ni * 8 + g]);
                bh1[ni] = fbits(Bh[ko + tg + 4][no + ni * 8 + g]);
                bl0[ni] = fbits(Bl[ko + tg][no + ni * 8 + g]);
                bl1[ni] = fbits(Bl[ko + tg + 4][no + ni * 8 + g]);
            }
            #pragma unroll
            for (int mi = 0; mi < 2; ++mi) {
                int mb = mo + mi * 16;
                uint32_t a0 = fbits(As[ko + tg][mb + g]);
                uint32_t a1 = fbits(As[ko + tg][mb + g + 8]);
                uint32_t a2 = fbits(As[ko + tg + 4][mb + g]);
                uint32_t a3 = fbits(As[ko + tg + 4][mb + g + 8]);
                #pragma unroll
                for (int ni = 0; ni < 4; ++ni) {
                    mma8(c[mi][ni], a0, a1, a2, a3, bh0[ni], bh1[ni]);
                    mma8(c[mi][ni], a0, a1, a2, a3, bl0[ni], bl1[ni]);
                }
            }
        }
        __syncthreads();
    }

    // colsum reduction -> g_de
    #pragma unroll
    for (int j = 0; j < 4; ++j) dsm[wid][am + j] = dsum[j];
    __syncthreads();
    if (wid == 0) {
        float s[4] = {0.f, 0.f, 0.f, 0.f};
        #pragma unroll
        for (int w = 0; w < 8; ++w)
            #pragma unroll
            for (int j = 0; j < 4; ++j) s[j] += dsm[w][am + j];
        #pragma unroll
        for (int j = 0; j < 4; ++j) {
            int e = e0 + am + j;
            if (e < EE) atomicAdd(&g_de[e], s[j]);
        }
    }

    // accumulate edge tiles
    #pragma unroll
    for (int mi = 0; mi < 2; ++mi) {
        #pragma unroll
        for (int ni = 0; ni < 4; ++ni) {
            int er0 = e0 + mo + mi * 16 + g;
            int er1 = er0 + 8;
            int col = no + ni * 8 + 2 * tg;
            if (er0 < EE) {
                atomicAdd(&g_edge[er0 * OC + col],     c[mi][ni][0]);
                atomicAdd(&g_edge[er0 * OC + col + 1], c[mi][ni][1]);
            }
            if (er1 < EE) {
                atomicAdd(&g_edge[er1 * OC + col],     c[mi][ni][2]);
                atomicAdd(&g_edge[er1 * OC + col + 1], c[mi][ni][3]);
            }
        }
    }
}

// ---------------------------------------------------------------- edge/de -> hi/lo planes
__global__ void div_k() {
    int i = blockIdx.x * 256 + threadIdx.x;
    if (i < EE * OC) {
        float v = g_edge[i] / g_de[i >> 6];
        uint32_t h = f2tf(v);
        uint32_t l = f2tf(v - __uint_as_float(h));
        g_edgeh[i] = __uint_as_float(h);
        g_edgel[i] = __uint_as_float(l);
    }
}

// ---------------------------------------------------------------- pass3: out = (H @ edge) / rowsum(H)
__global__ __launch_bounds__(256, 2) void pass3_k(const float* __restrict__ H,
                                                  float* __restrict__ out) {
    __shared__ float As[128][36];   // [n_local][k] raw(scaled) H; bank-safe stride
    __shared__ float Bh[32][72];    // [k][c] edge hi
    __shared__ float Bl[32][72];    // [k][c] edge lo
    __shared__ float dn_s[128];

    int tid  = threadIdx.x;
    int lane = tid & 31, wid = tid >> 5;
    int n0   = blockIdx.x * 128;
    int wm   = wid >> 1, wn = wid & 1;
    int mo   = wm * 32,  no = wn * 32;
    int g    = lane >> 2, tg = lane & 3;

    int row = tid >> 1, s = tid & 1;
    int gn  = n0 + row;
    bool rok = (gn < NN);
    int bk = tid >> 4, bn = 4 * (tid & 15);

    float4 pa[4], pbh[2], pbl[2];
    float rsum = 0.f;
    float c[2][4][4];
    #pragma unroll
    for (int mi = 0; mi < 2; ++mi)
        #pragma unroll
        for (int ni = 0; ni < 4; ++ni)
            #pragma unroll
            for (int j = 0; j < 4; ++j) c[mi][ni][j] = 0.f;

    const int KT = (EE + 31) / 32;   // 313

    // prefetch first tile
    {
        #pragma unroll
        for (int i = 0; i < 4; ++i) {
            int k = (s * 4 + i) * 4;
            pa[i] = (rok && k + 4 <= EE) ? *(const float4*)&H[(long)gn * EE + k]
                                         : make_float4(0.f, 0.f, 0.f, 0.f);
        }
        #pragma unroll
        for (int it = 0; it < 2; ++it) {
            int k = bk + 16 * it;
            if (k < EE) {
                long base = (long)k * OC + bn;
                pbh[it] = *(const float4*)&g_edgeh[base];
                pbl[it] = *(const float4*)&g_edgel[base];
            } else {
                pbh[it] = make_float4(0.f, 0.f, 0.f, 0.f);
                pbl[it] = make_float4(0.f, 0.f, 0.f, 0.f);
            }
        }
    }

    for (int t = 0; t < KT; ++t) {
        #pragma unroll
        for (int i = 0; i < 4; ++i) {
            rsum += pa[i].x + pa[i].y + pa[i].z + pa[i].w;
            float4 sv;
            sv.x = pa[i].x * CENTER; sv.y = pa[i].y * CENTER;
            sv.z = pa[i].z * CENTER; sv.w = pa[i].w * CENTER;
            *(float4*)&As[row][(s * 4 + i) * 4] = sv;
        }
        #pragma unroll
        for (int it = 0; it < 2; ++it) {
            int r = bk + 16 * it;
            *(float4*)&Bh[r][bn] = pbh[it];
            *(float4*)&Bl[r][bn] = pbl[it];
        }
        __syncthreads();

        if (t + 1 < KT) {
            int k0 = (t + 1) * 32;
            #pragma unroll
            for (int i = 0; i < 4; ++i) {
                int k = k0 + (s * 4 + i) * 4;
                pa[i] = (rok && k + 4 <= EE) ? *(const float4*)&H[(long)gn * EE + k]
                                             : make_float4(0.f, 0.f, 0.f, 0.f);
            }
            #pragma unroll
            for (int it = 0; it < 2; ++it) {
                int k = k0 + bk + 16 * it;
                if (k < EE) {
                    long base = (long)k * OC + bn;
                    pbh[it] = *(const float4*)&g_edgeh[base];
                    pbl[it] = *(const float4*)&g_edgel[base];
                } else {
                    pbh[it] = make_float4(0.f, 0.f, 0.f, 0.f);
                    pbl[it] = make_float4(0.f, 0.f, 0.f, 0.f);
                }
            }
        }

        #pragma unroll
        for (int ko = 0; ko < 32; ko += 8) {
            uint32_t bh0[4], bh1[4], bl0[4], bl1[4];
            #pragma unroll
            for (int ni = 0; ni < 4; ++ni) {
                bh0[ni] = fbits(Bh[ko + tg][no + ni * 8 + g]);
                bh1[ni] = fbits(Bh[ko + tg + 4][no + ni * 8 + g]);
                bl0[ni] = fbits(Bl[ko + tg][no + ni * 8 + g]);
                bl1[ni] = fbits(Bl[ko + tg + 4][no + ni * 8 + g]);
            }
            #pragma unroll
            for (int mi = 0; mi < 2; ++mi) {
                int mb = mo + mi * 16;
                uint32_t a0 = fbits(As[mb + g][ko + tg]);
                uint32_t a1 = fbits(As[mb + g + 8][ko + tg]);
                uint32_t a2 = fbits(As[mb + g][ko + tg + 4]);
                uint32_t a3 = fbits(As[mb + g + 8][ko + tg + 4]);
                #pragma unroll
                for (int ni = 0; ni < 4; ++ni) {
                    mma8(c[mi][ni], a0, a1, a2, a3, bh0[ni], bh1[ni]);
                    mma8(c[mi][ni], a0, a1, a2, a3, bl0[ni], bl1[ni]);
                }
            }
        }
        __syncthreads();
    }

    // row degree
    float tot = rsum + __shfl_xor_sync(0xffffffffu, rsum, 1);
    if (s == 0) dn_s[row] = tot;
    __syncthreads();

    #pragma unroll
    for (int mi = 0; mi < 2; ++mi) {
        #pragma unroll
        for (int ni = 0; ni < 4; ++ni) {
            int r0  = mo + mi * 16 + g;
            int r1  = r0 + 8;
            int col = no + ni * 8 + 2 * tg;
            if (n0 + r0 < NN) {
                float inv = 1.0f / dn_s[r0];
                out[(long)(n0 + r0) * OC + col]     = c[mi][ni][0] * inv;
                out[(long)(n0 + r0) * OC + col + 1] = c[mi][ni][1] * inv;
            }
            if (n0 + r1 < NN) {
                float inv = 1.0f / dn_s[r1];
                out[(long)(n0 + r1) * OC + col]     = c[mi][ni][2] * inv;
                out[(long)(n0 + r1) * OC + col + 1] = c[mi][ni][3] * inv;
            }
        }
    }
}

// ---------------------------------------------------------------- launch
extern "C" void kernel_launch(void* const* d_in, const int* in_sizes, int n_in,
                              void* d_out, int out_size) {
    const float* x  = (const float*)d_in[0];   // [N, 128]
    const float* H  = (const float*)d_in[1];   // [N, E]
    const float* th = (const float*)d_in[2];   // [128, 64]
    float* out = (float*)d_out;                // [N, 64]

    zero_k<<<(EE * OC + 255) / 256, 256>>>();
    xt_k<<<NN / 4, 256>>>(x, th);
    dim3 g2((EE + 127) / 128, SPLIT2);
    pass2_k<<<g2, 256>>>(H);
    div_k<<<(EE * OC + 255) / 256, 256>>>();
    pass3_k<<<(NN + 127) / 128, 256>>>(H, out);
}

// round 16
// speedup vs baseline: 2.3355x; 1.3126x over previous
#include <cuda_runtime.h>
#include <cuda_bf16.h>
#include <cstdint>

#define NN 20000
#define EE 10000
#define IC 128
#define OC 64
#define SPLIT2 8

// Scratch (no allocations allowed)
__device__ __nv_bfloat16 g_xth[NN * OC];   // xt bf16 hi plane [n][c]
__device__ __nv_bfloat16 g_xtl[NN * OC];   // xt bf16 lo plane [n][c]
__device__ float g_edge[EE * OC];          // f32 accumulator (atomics)
__device__ __nv_bfloat16 g_eh[EE * OC];    // edge bf16 hi plane [e][c]
__device__ __nv_bfloat16 g_el[EE * OC];    // edge bf16 lo plane [e][c]
__device__ float g_de[EE];

// ---------------------------------------------------------------- helpers
// pack two f32 -> bf16x2: LOW half = a (k even), HIGH half = b (k odd)
__device__ __forceinline__ uint32_t packp(float a, float b) {
    uint32_t r;
    asm("cvt.rn.bf16x2.f32 %0, %1, %2;" : "=r"(r) : "f"(b), "f"(a));
    return r;
}
__device__ __forceinline__ float lowf(uint32_t u)  { return __uint_as_float(u << 16); }
__device__ __forceinline__ float highf(uint32_t u) { return __uint_as_float(u & 0xFFFF0000u); }
__device__ __forceinline__ uint32_t prmtf(uint32_t a, uint32_t b, uint32_t s) {
    uint32_t d;
    asm("prmt.b32 %0, %1, %2, %3;" : "=r"(d) : "r"(a), "r"(b), "r"(s));
    return d;
}
__device__ __forceinline__ void mma16(float* c,
                                      uint32_t a0, uint32_t a1, uint32_t a2, uint32_t a3,
                                      uint32_t b0, uint32_t b1) {
    asm volatile(
        "mma.sync.aligned.m16n8k16.row.col.f32.bf16.bf16.f32 "
        "{%0,%1,%2,%3},{%4,%5,%6,%7},{%8,%9},{%0,%1,%2,%3};"
        : "+f"(c[0]), "+f"(c[1]), "+f"(c[2]), "+f"(c[3])
        : "r"(a0), "r"(a1), "r"(a2), "r"(a3), "r"(b0), "r"(b1));
}

// ---------------------------------------------------------------- zero + ncu-shift probe
__global__ void zero_k() {
    int i = blockIdx.x * 256 + threadIdx.x;
    if (i < EE * OC) g_edge[i] = 0.0f;
    if (i < EE)      g_de[i]   = 0.0f;
}
__global__ void probe_k() {}   // shifts ncu -s5 capture onto pass2

// ---------------------------------------------------------------- xt = x @ theta -> bf16 hi/lo
__global__ void xt_k(const float* __restrict__ x, const float* __restrict__ th) {
    __shared__ float ths[IC * OC];
    int tid = threadIdx.x;
    #pragma unroll
    for (int i = tid; i < IC * OC; i += 256) ths[i] = th[i];
    __syncthreads();

    int n = blockIdx.x * 4 + (tid >> 6);
    int c = tid & 63;
    const float* xr = x + (size_t)n * IC;
    float acc = 0.0f;
    #pragma unroll 8
    for (int k = 0; k < IC; ++k) acc += xr[k] * ths[k * OC + c];
    __nv_bfloat16 h = __float2bfloat16_rn(acc);
    g_xth[n * OC + c] = h;
    g_xtl[n * OC + c] = __float2bfloat16_rn(acc - __bfloat162float(h));
}

// ---------------------------------------------------------------- pass2: edge += H^T @ xt ; de += colsum(H)
__global__ __launch_bounds__(256, 2) void pass2_k(const float* __restrict__ H) {
    __shared__ uint32_t Ah[16][136], Al[16][136];   // [k2][e] bf16x2 pairs along k
    __shared__ uint32_t Bh[16][72],  Bl[16][72];    // [k2][c]
    __shared__ float dsm[8][128];

    int tid  = threadIdx.x;
    int lane = tid & 31, wid = tid >> 5;
    int e0   = blockIdx.x * 128;
    int wm   = wid >> 1, wn = wid & 1;
    int mo   = wm * 32,  no = wn * 32;
    int g    = lane >> 2, tg = lane & 3;

    const int TILES = NN / 32;
    const int TPC   = (TILES + SPLIT2 - 1) / SPLIT2;
    int t0 = blockIdx.y * TPC;
    int t1 = t0 + TPC; if (t1 > TILES) t1 = TILES;

    int lrow = tid >> 5, lc = tid & 31, am = 4 * lc;
    bool eok = (e0 + am + 4 <= EE);
    int bk2 = tid >> 4, bc = 4 * (tid & 15);

    float4 r0[2], r1[2];
    uint2 phe, pho, ple, plo;
    float dsum[4] = {0.f, 0.f, 0.f, 0.f};
    float c[2][4][4];
    #pragma unroll
    for (int mi = 0; mi < 2; ++mi)
        #pragma unroll
        for (int ni = 0; ni < 4; ++ni)
            #pragma unroll
            for (int j = 0; j < 4; ++j) c[mi][ni][j] = 0.f;

    {
        int k0 = t0 * 32;
        #pragma unroll
        for (int s = 0; s < 2; ++s) {
            int ke = k0 + 2 * (lrow + 8 * s);
            r0[s] = eok ? *(const float4*)&H[(long)ke * EE + e0 + am]
                        : make_float4(0.f, 0.f, 0.f, 0.f);
            r1[s] = eok ? *(const float4*)&H[(long)(ke + 1) * EE + e0 + am]
                        : make_float4(0.f, 0.f, 0.f, 0.f);
        }
        int ne = k0 + 2 * bk2;
        phe = *(const uint2*)&g_xth[(long)ne * OC + bc];
        pho = *(const uint2*)&g_xth[(long)(ne + 1) * OC + bc];
        ple = *(const uint2*)&g_xtl[(long)ne * OC + bc];
        plo = *(const uint2*)&g_xtl[(long)(ne + 1) * OC + bc];
    }

    for (int t = t0; t < t1; ++t) {
        #pragma unroll
        for (int s = 0; s < 2; ++s) {
            int k2 = lrow + 8 * s;
            float4 a = r0[s], b = r1[s];
            dsum[0] += a.x + b.x; dsum[1] += a.y + b.y;
            dsum[2] += a.z + b.z; dsum[3] += a.w + b.w;
            uint32_t h0 = packp(a.x, b.x), h1 = packp(a.y, b.y);
            uint32_t h2 = packp(a.z, b.z), h3 = packp(a.w, b.w);
            *(uint4*)&Ah[k2][am] = make_uint4(h0, h1, h2, h3);
            uint32_t l0 = packp(a.x - lowf(h0), b.x - highf(h0));
            uint32_t l1 = packp(a.y - lowf(h1), b.y - highf(h1));
            uint32_t l2 = packp(a.z - lowf(h2), b.z - highf(h2));
            uint32_t l3 = packp(a.w - lowf(h3), b.w - highf(h3));
            *(uint4*)&Al[k2][am] = make_uint4(l0, l1, l2, l3);
        }
        {
            uint32_t o0 = prmtf(phe.x, pho.x, 0x5410), o1 = prmtf(phe.x, pho.x, 0x7632);
            uint32_t o2 = prmtf(phe.y, pho.y, 0x5410), o3 = prmtf(phe.y, pho.y, 0x7632);
            *(uint4*)&Bh[bk2][bc] = make_uint4(o0, o1, o2, o3);
            o0 = prmtf(ple.x, plo.x, 0x5410); o1 = prmtf(ple.x, plo.x, 0x7632);
            o2 = prmtf(ple.y, plo.y, 0x5410); o3 = prmtf(ple.y, plo.y, 0x7632);
            *(uint4*)&Bl[bk2][bc] = make_uint4(o0, o1, o2, o3);
        }
        __syncthreads();

        if (t + 1 < t1) {
            int k0 = (t + 1) * 32;
            #pragma unroll
            for (int s = 0; s < 2; ++s) {
                int ke = k0 + 2 * (lrow + 8 * s);
                r0[s] = eok ? *(const float4*)&H[(long)ke * EE + e0 + am]
                            : make_float4(0.f, 0.f, 0.f, 0.f);
                r1[s] = eok ? *(const float4*)&H[(long)(ke + 1) * EE + e0 + am]
                            : make_float4(0.f, 0.f, 0.f, 0.f);
            }
            int ne = k0 + 2 * bk2;
            phe = *(const uint2*)&g_xth[(long)ne * OC + bc];
            pho = *(const uint2*)&g_xth[(long)(ne + 1) * OC + bc];
            ple = *(const uint2*)&g_xtl[(long)ne * OC + bc];
            plo = *(const uint2*)&g_xtl[(long)(ne + 1) * OC + bc];
        }

        #pragma unroll
        for (int ko2 = 0; ko2 < 16; ko2 += 8) {
            uint32_t bh0[4], bh1[4], bl0[4], bl1[4];
            #pragma unroll
            for (int ni = 0; ni < 4; ++ni) {
                int col = no + ni * 8 + g;
                bh0[ni] = Bh[ko2 + tg][col];
                bh1[ni] = Bh[ko2 + tg + 4][col];
                bl0[ni] = Bl[ko2 + tg][col];
                bl1[ni] = Bl[ko2 + tg + 4][col];
            }
            #pragma unroll
            for (int mi = 0; mi < 2; ++mi) {
                int mb = mo + mi * 16;
                uint32_t ah0 = Ah[ko2 + tg][mb + g];
                uint32_t ah1 = Ah[ko2 + tg][mb + g + 8];
                uint32_t ah2 = Ah[ko2 + tg + 4][mb + g];
                uint32_t ah3 = Ah[ko2 + tg + 4][mb + g + 8];
                uint32_t al0 = Al[ko2 + tg][mb + g];
                uint32_t al1 = Al[ko2 + tg][mb + g + 8];
                uint32_t al2 = Al[ko2 + tg + 4][mb + g];
                uint32_t al3 = Al[ko2 + tg + 4][mb + g + 8];
                #pragma unroll
                for (int ni = 0; ni < 4; ++ni) {
                    mma16(c[mi][ni], ah0, ah1, ah2, ah3, bh0[ni], bh1[ni]);
                    mma16(c[mi][ni], ah0, ah1, ah2, ah3, bl0[ni], bl1[ni]);
                    mma16(c[mi][ni], al0, al1, al2, al3, bh0[ni], bh1[ni]);
                }
            }
        }
        __syncthreads();
    }

    #pragma unroll
    for (int j = 0; j < 4; ++j) dsm[lrow][am + j] = dsum[j];
    __syncthreads();
    if (wid == 0) {
        float s[4] = {0.f, 0.f, 0.f, 0.f};
        #pragma unroll
        for (int w = 0; w < 8; ++w)
            #pragma unroll
            for (int j = 0; j < 4; ++j) s[j] += dsm[w][4 * lane + j];
        #pragma unroll
        for (int j = 0; j < 4; ++j) {
            int e = e0 + 4 * lane + j;
            if (e < EE) atomicAdd(&g_de[e], s[j]);
        }
    }

    #pragma unroll
    for (int mi = 0; mi < 2; ++mi) {
        #pragma unroll
        for (int ni = 0; ni < 4; ++ni) {
            int er0 = e0 + mo + mi * 16 + g;
            int er1 = er0 + 8;
            int col = no + ni * 8 + 2 * tg;
            if (er0 < EE) {
                atomicAdd(&g_edge[er0 * OC + col],     c[mi][ni][0]);
                atomicAdd(&g_edge[er0 * OC + col + 1], c[mi][ni][1]);
            }
            if (er1 < EE) {
                atomicAdd(&g_edge[er1 * OC + col],     c[mi][ni][2]);
                atomicAdd(&g_edge[er1 * OC + col + 1], c[mi][ni][3]);
            }
        }
    }
}

// ---------------------------------------------------------------- edge/de -> bf16 hi/lo planes
__global__ void div_k() {
    int i = blockIdx.x * 256 + threadIdx.x;
    if (i < EE * OC) {
        float v = g_edge[i] / g_de[i >> 6];
        __nv_bfloat16 h = __float2bfloat16_rn(v);
        g_eh[i] = h;
        g_el[i] = __float2bfloat16_rn(v - __bfloat162float(h));
    }
}

// ---------------------------------------------------------------- pass3: out = (H @ edge) / rowsum(H)
__global__ __launch_bounds__(256, 2) void pass3_k(const float* __restrict__ H,
                                                  float* __restrict__ out) {
    __shared__ uint32_t Ah[16][136], Al[16][136];   // [k2][n_local]
    __shared__ uint32_t Bh[16][72],  Bl[16][72];    // [k2][c]
    __shared__ float dn_s[128];

    int tid  = threadIdx.x;
    int lane = tid & 31, wid = tid >> 5;
    int n0   = blockIdx.x * 128;
    int wm   = wid >> 1, wn = wid & 1;
    int mo   = wm * 32,  no = wn * 32;
    int g    = lane >> 2, tg = lane & 3;

    if (tid < 128) dn_s[tid] = 0.f;

    int bk2 = tid >> 4, bc = 4 * (tid & 15);

    float4 pa[4];
    uint2 phe, pho, ple, plo;
    float rs4[4] = {0.f, 0.f, 0.f, 0.f};   // per-row partials (rows tid>>3 + 32*i)
    float c[2][4][4];
    #pragma unroll
    for (int mi = 0; mi < 2; ++mi)
        #pragma unroll
        for (int ni = 0; ni < 4; ++ni)
            #pragma unroll
            for (int j = 0; j < 4; ++j) c[mi][ni][j] = 0.f;

    const int KT = (EE + 31) / 32;

    {
        #pragma unroll
        for (int i = 0; i < 4; ++i) {
            int idx = tid + 256 * i;
            int row = idx >> 3, f4 = idx & 7;
            int gn = n0 + row, k = f4 * 4;
            pa[i] = (gn < NN && k + 4 <= EE) ? *(const float4*)&H[(long)gn * EE + k]
                                             : make_float4(0.f, 0.f, 0.f, 0.f);
        }
        int e = 2 * bk2;
        bool bok = (e + 1 < EE);
        phe = bok ? *(const uint2*)&g_eh[(long)e * OC + bc] : make_uint2(0, 0);
        pho = bok ? *(const uint2*)&g_eh[(long)(e + 1) * OC + bc] : make_uint2(0, 0);
        ple = bok ? *(const uint2*)&g_el[(long)e * OC + bc] : make_uint2(0, 0);
        plo = bok ? *(const uint2*)&g_el[(long)(e + 1) * OC + bc] : make_uint2(0, 0);
    }

    for (int t = 0; t < KT; ++t) {
        #pragma unroll
        for (int i = 0; i < 4; ++i) {
            int idx = tid + 256 * i;
            int row = idx >> 3, f4 = idx & 7;
            float4 v = pa[i];
            rs4[i] += v.x + v.y + v.z + v.w;
            uint32_t h0 = packp(v.x, v.y), h1 = packp(v.z, v.w);
            Ah[2 * f4][row]     = h0;
            Ah[2 * f4 + 1][row] = h1;
            Al[2 * f4][row]     = packp(v.x - lowf(h0), v.y - highf(h0));
            Al[2 * f4 + 1][row] = packp(v.z - lowf(h1), v.w - highf(h1));
        }
        {
            uint32_t o0 = prmtf(phe.x, pho.x, 0x5410), o1 = prmtf(phe.x, pho.x, 0x7632);
            uint32_t o2 = prmtf(phe.y, pho.y, 0x5410), o3 = prmtf(phe.y, pho.y, 0x7632);
            *(uint4*)&Bh[bk2][bc] = make_uint4(o0, o1, o2, o3);
            o0 = prmtf(ple.x, plo.x, 0x5410); o1 = prmtf(ple.x, plo.x, 0x7632);
            o2 = prmtf(ple.y, plo.y, 0x5410); o3 = prmtf(ple.y, plo.y, 0x7632);
            *(uint4*)&Bl[bk2][bc] = make_uint4(o0, o1, o2, o3);
        }
        __syncthreads();

        if (t + 1 < KT) {
            int k0 = (t + 1) * 32;
            #pragma unroll
            for (int i = 0; i < 4; ++i) {
                int idx = tid + 256 * i;
                int row = idx >> 3, f4 = idx & 7;
                int gn = n0 + row, k = k0 + f4 * 4;
                pa[i] = (gn < NN && k + 4 <= EE) ? *(const float4*)&H[(long)gn * EE + k]
                                                 : make_float4(0.f, 0.f, 0.f, 0.f);
            }
            int e = k0 + 2 * bk2;
            bool bok = (e + 1 < EE);
            phe = bok ? *(const uint2*)&g_eh[(long)e * OC + bc] : make_uint2(0, 0);
            pho = bok ? *(const uint2*)&g_eh[(long)(e + 1) * OC + bc] : make_uint2(0, 0);
            ple = bok ? *(const uint2*)&g_el[(long)e * OC + bc] : make_uint2(0, 0);
            plo = bok ? *(const uint2*)&g_el[(long)(e + 1) * OC + bc] : make_uint2(0, 0);
        }

        #pragma unroll
        for (int ko2 = 0; ko2 < 16; ko2 += 8) {
            uint32_t bh0[4], bh1[4], bl0[4], bl1[4];
            #pragma unroll
            for (int ni = 0; ni < 4; ++ni) {
                int col = no + ni * 8 + g;
                bh0[ni] = Bh[ko2 + tg][col];
                bh1[ni] = Bh[ko2 + tg + 4][col];
                bl0[ni] = Bl[ko2 + tg][col];
                bl1[ni] = Bl[ko2 + tg + 4][col];
            }
            #pragma unroll
            for (int mi = 0; mi < 2; ++mi) {
                int mb = mo + mi * 16;
                uint32_t ah0 = Ah[ko2 + tg][mb + g];
                uint32_t ah1 = Ah[ko2 + tg][mb + g + 8];
                uint32_t ah2 = Ah[ko2 + tg + 4][mb + g];
                uint32_t ah3 = Ah[ko2 + tg + 4][mb + g + 8];
                uint32_t al0 = Al[ko2 + tg][mb + g];
                uint32_t al1 = Al[ko2 + tg][mb + g + 8];
                uint32_t al2 = Al[ko2 + tg + 4][mb + g];
                uint32_t al3 = Al[ko2 + tg + 4][mb + g + 8];
                #pragma unroll
                for (int ni = 0; ni < 4; ++ni) {
                    mma16(c[mi][ni], ah0, ah1, ah2, ah3, bh0[ni], bh1[ni]);
                    mma16(c[mi][ni], ah0, ah1, ah2, ah3, bl0[ni], bl1[ni]);
                    mma16(c[mi][ni], al0, al1, al2, al3, bh0[ni], bh1[ni]);
                }
            }
        }
        __syncthreads();
    }

    // row degrees: reduce 8 loader-lanes per row (lanes tid&7 share a row)
    #pragma unroll
    for (int i = 0; i < 4; ++i) {
        float v = rs4[i];
        v += __shfl_xor_sync(0xffffffffu, v, 1);
        v += __shfl_xor_sync(0xffffffffu, v, 2);
        v += __shfl_xor_sync(0xffffffffu, v, 4);
        if ((tid & 7) == 0) dn_s[(tid >> 3) + 32 * i] = v;
    }
    __syncthreads();

    #pragma unroll
    for (int mi = 0; mi < 2; ++mi) {
        #pragma unroll
        for (int ni = 0; ni < 4; ++ni) {
            int r0  = mo + mi * 16 + g;
            int r1  = r0 + 8;
            int col = no + ni * 8 + 2 * tg;
            if (n0 + r0 < NN) {
                float inv = 1.0f / dn_s[r0];
                out[(long)(n0 + r0) * OC + col]     = c[mi][ni][0] * inv;
                out[(long)(n0 + r0) * OC + col + 1] = c[mi][ni][1] * inv;
            }
            if (n0 + r1 < NN) {
                float inv = 1.0f / dn_s[r1];
                out[(long)(n0 + r1) * OC + col]     = c[mi][ni][2] * inv;
                out[(long)(n0 + r1) * OC + col + 1] = c[mi][ni][3] * inv;
            }
        }
    }
}

// ---------------------------------------------------------------- launch
extern "C" void kernel_launch(void* const* d_in, const int* in_sizes, int n_in,
                              void* d_out, int out_size) {
    const float* x  = (const float*)d_in[0];   // [N, 128]
    const float* H  = (const float*)d_in[1];   // [N, E]
    const float* th = (const float*)d_in[2];   // [128, 64]
    float* out = (float*)d_out;                // [N, 64]

    zero_k<<<(EE * OC + 255) / 256, 256>>>();
    probe_k<<<1, 32>>>();
    xt_k<<<NN / 4, 256>>>(x, th);
    dim3 g2((EE + 127) / 128, SPLIT2);
    pass2_k<<<g2, 256>>>(H);
    div_k<<<(EE * OC + 255) / 256, 256>>>();
    pass3_k<<<(NN + 127) / 128, 256>>>(H, out);
}